// round 5
// baseline (speedup 1.0000x reference)
#include <cuda_runtime.h>
#include <cuda_bf16.h>
#include <cstdint>
#include <math.h>

#define NROWS   8192
#define DIM     128
#define KSLAB   128                  // K-rows per gram task
#define NSLAB   (NROWS / KSLAB)      // 64
#define NTASK   (3 * NSLAB)          // 192
#define NB      96                   // persistent blocks (all co-resident)
#define PITCH   136                  // bf16 tile pitch (17x16B: ldmatrix conflict-free)

// ---------------- device globals (no allocs allowed) ----------------------
__device__ float    g_part[3][NSLAB][DIM * DIM]; // partial grams (permuted layout)
__device__ double   g_bsum[64];
__device__ unsigned g_bar[3];                    // [0],[1] barriers, [2] done

__device__ __forceinline__ uint32_t smem_u32(const void* p) {
    uint32_t a;
    asm("{ .reg .u64 t; cvta.to.shared.u64 t, %1; cvt.u32.u64 %0, t; }"
        : "=r"(a) : "l"(p));
    return a;
}

#define LDMX4(r0, r1, r2, r3, addr) \
    asm volatile("ldmatrix.sync.aligned.m8n8.x4.shared.b16 {%0,%1,%2,%3}, [%4];" \
        : "=r"(r0), "=r"(r1), "=r"(r2), "=r"(r3) : "r"(addr))

#define MMA16816(d, a, b) \
    asm volatile("mma.sync.aligned.m16n8k16.row.col.f32.bf16.bf16.f32 " \
        "{%0,%1,%2,%3}, {%4,%5,%6,%7}, {%8,%9}, {%0,%1,%2,%3};" \
        : "+f"((d)[0]), "+f"((d)[1]), "+f"((d)[2]), "+f"((d)[3]) \
        : "r"((a)[0]), "r"((a)[1]), "r"((a)[2]), "r"((a)[3]), \
          "r"((b)[0]), "r"((b)[1]))

// smem: stage f32 [128][129] | sInv[128] | tileA bf16 [128][136] | tileB
#define STAGE_F32  (DIM * 129)                    // 16512 floats
#define TILE_ELEMS (DIM * PITCH)                  // 17408 bf16
#define FSMEM      (STAGE_F32 * 4 + DIM * 4 + 2 * TILE_ELEMS * 2)  // 136192

// device-wide barrier (all NB blocks resident by construction)
__device__ __forceinline__ void gbar(int id) {
    __syncthreads();
    if (threadIdx.x == 0) {
        __threadfence();
        atomicAdd(&g_bar[id], 1u);
        while (*(volatile unsigned*)&g_bar[id] < NB) __nanosleep(32);
        __threadfence();
    }
    __syncthreads();
}

// normalize 128-row f32 slab and write bf16 transposed tile (dim-major)
__device__ __forceinline__ void build_tile(const float* __restrict__ src,
                                           float* stage, float* sInv,
                                           __nv_bfloat16* dst,
                                           int t, int lane)
{
    // load 128x128 f32; warp w at iter i owns row i*8+w fully -> shfl norm
#pragma unroll
    for (int i = 0; i < 16; i++) {
        int f4 = i * 256 + t;
        int row = f4 >> 5, c4 = f4 & 31;
        float4 v = reinterpret_cast<const float4*>(src)[f4];
        float* p = stage + row * 129 + c4 * 4;
        p[0] = v.x; p[1] = v.y; p[2] = v.z; p[3] = v.w;
        float s = v.x * v.x + v.y * v.y + v.z * v.z + v.w * v.w;
#pragma unroll
        for (int off = 16; off > 0; off >>= 1)
            s += __shfl_xor_sync(0xffffffffu, s, off);
        if (lane == 0)
            sInv[row] = 1.0f / fmaxf(sqrtf(s), 1e-8f);
    }
    __syncthreads();
    // transposed bf16 store: dst[d][r], 2-way LDS conflicts on column reads
#pragma unroll
    for (int i = 0; i < 32; i++) {
        int idx = i * 256 + t;
        int d = idx >> 6, rp = idx & 63;
        int r0 = rp * 2, r1 = r0 + 1;
        float v0 = stage[r0 * 129 + d] * sInv[r0];
        float v1 = stage[r1 * 129 + d] * sInv[r1];
        *reinterpret_cast<__nv_bfloat162*>(&dst[d * PITCH + r0])
            = __floats2bfloat162_rn(v0, v1);
    }
    __syncthreads();
}

extern "C" __global__ void __launch_bounds__(256)
fused_kernel(const float* __restrict__ Q, const float* __restrict__ K,
             float* __restrict__ out)
{
    extern __shared__ char smem[];
    float* stage = reinterpret_cast<float*>(smem);
    float* sInv  = stage + STAGE_F32;
    __nv_bfloat16* tA = reinterpret_cast<__nv_bfloat16*>(sInv + DIM);
    __nv_bfloat16* tB = tA + TILE_ELEMS;
    const uint32_t sAaddr = smem_u32(tA);
    const uint32_t sBaddr = smem_u32(tB);

    const int t    = threadIdx.x;
    const int lane = t & 31;
    const int w    = t >> 5;
    const int bid  = blockIdx.x;

    // ---- phase 1: gram tasks (conv fused in) ------------------------------
    for (int task = bid; task < NTASK; task += NB) {
        const int gram = task >> 6;          // 0=QQ, 1=KK, 2=QK
        const int slab = task & 63;
        const float* srcA = ((gram == 1) ? K : Q) + (size_t)slab * KSLAB * DIM;

        build_tile(srcA, stage, sInv, tA, t, lane);
        if (gram == 2)
            build_tile(K + (size_t)slab * KSLAB * DIM, stage, sInv, tB, t, lane);
        const uint32_t sB_use = (gram == 2) ? sBaddr : sAaddr;

        // warp tile: 32 M-rows x 64 N-cols
        const int m0 = (w & 3) * 32;
        const int n0 = (w >> 2) * 64;
        const int aRow  = m0 + (lane & 15);
        const int aKoff = (lane >> 4) * 8;
        const int bNoff = (lane & 7) + ((lane >> 4) & 1) * 8;
        const int bKoff = ((lane >> 3) & 1) * 8;

        float acc[2][8][4];
#pragma unroll
        for (int mt = 0; mt < 2; mt++)
#pragma unroll
            for (int nt = 0; nt < 8; nt++)
#pragma unroll
                for (int r = 0; r < 4; r++) acc[mt][nt][r] = 0.0f;

#pragma unroll
        for (int ks = 0; ks < 8; ks++) {
            const int k0 = ks * 16;
            uint32_t a[2][4];
#pragma unroll
            for (int mt = 0; mt < 2; mt++) {
                uint32_t addr = sAaddr
                    + (uint32_t)(((aRow + mt * 16) * PITCH) + k0 + aKoff) * 2;
                LDMX4(a[mt][0], a[mt][1], a[mt][2], a[mt][3], addr);
            }
            uint32_t b[8][2];
#pragma unroll
            for (int nt4 = 0; nt4 < 4; nt4++) {
                uint32_t addr = sB_use
                    + (uint32_t)(((n0 + nt4 * 16 + bNoff) * PITCH) + k0 + bKoff) * 2;
                uint32_t r0, r1, r2, r3;
                LDMX4(r0, r1, r2, r3, addr);
                b[nt4 * 2][0] = r0;     b[nt4 * 2][1] = r1;
                b[nt4 * 2 + 1][0] = r2; b[nt4 * 2 + 1][1] = r3;
            }
#pragma unroll
            for (int mt = 0; mt < 2; mt++)
#pragma unroll
                for (int nt = 0; nt < 8; nt++)
                    MMA16816(acc[mt][nt], a[mt], b[nt]);
        }

        // permuted-coalesced partial store (same permutation for every task)
        float* outp = &g_part[gram][slab][0];
#pragma unroll
        for (int mt = 0; mt < 2; mt++)
#pragma unroll
            for (int nt = 0; nt < 8; nt++)
#pragma unroll
                for (int r = 0; r < 4; r++)
                    outp[w * 2048 + (mt * 8 + nt) * 128 + r * 32 + lane]
                        = acc[mt][nt][r];
    }

    gbar(0);

    // ---- phase 2: reduce over slabs (blocks 0..63) ------------------------
    if (bid < 64) {
        const int idx = bid * 256 + t;                  // [0, 16384)
        const float* p0 = &g_part[0][0][0];
        const float* p1 = &g_part[1][0][0];
        const float* p2 = &g_part[2][0][0];
        double sq = 0.0, sk = 0.0, sx = 0.0;
#pragma unroll 8
        for (int s = 0; s < NSLAB; s++) {
            sq += (double)p0[s * 16384 + idx];
            sk += (double)p1[s * 16384 + idx];
            sx += (double)p2[s * 16384 + idx];
        }
        double c = sq * sq + sk * sk - 2.0 * sx * sx;
#pragma unroll
        for (int off = 16; off > 0; off >>= 1)
            c += __shfl_xor_sync(0xffffffffu, c, off);

        __shared__ double wsum[8];
        if (lane == 0) wsum[w] = c;
        __syncthreads();
        if (t == 0) {
            double s = 0.0;
#pragma unroll
            for (int ww = 0; ww < 8; ww++) s += wsum[ww];
            g_bsum[bid] = s;
        }
    }

    gbar(1);

    // ---- phase 3: final scalar (block 0) ----------------------------------
    if (bid == 0 && w == 0) {
        double s = g_bsum[lane] + g_bsum[lane + 32];
#pragma unroll
        for (int off = 16; off > 0; off >>= 1)
            s += __shfl_xor_sync(0xffffffffu, s, off);
        if (lane == 0)
            out[0] = (float)(s / (8192.0 * 8191.0));
    }

    // ---- exit protocol: self-resetting barriers across graph replays ------
    __syncthreads();
    if (t == 0) {
        __threadfence();
        atomicAdd(&g_bar[2], 1u);
        if (bid == 0) {
            // reset only after ALL blocks are past every barrier wait
            while (*(volatile unsigned*)&g_bar[2] < NB) __nanosleep(32);
            g_bar[0] = 0u;
            g_bar[1] = 0u;
            __threadfence();
            g_bar[2] = 0u;
        }
    }
}

extern "C" void kernel_launch(void* const* d_in, const int* in_sizes, int n_in,
                              void* d_out, int out_size)
{
    (void)in_sizes; (void)n_in; (void)out_size;
    const float* Q = (const float*)d_in[0];
    const float* K = (const float*)d_in[1];

    cudaFuncSetAttribute(fused_kernel,
                         cudaFuncAttributeMaxDynamicSharedMemorySize, FSMEM);
    fused_kernel<<<NB, 256, FSMEM>>>(Q, K, (float*)d_out);
}

// round 6
// speedup vs baseline: 1.2286x; 1.2286x over previous
#include <cuda_runtime.h>
#include <cuda_bf16.h>
#include <cstdint>
#include <math.h>

#define NROWS   8192
#define DIM     128
#define KSLAB   128                  // K-rows per gram task
#define NSLAB   (NROWS / KSLAB)      // 64
#define NTASK   (3 * NSLAB)          // 192
#define NB      192                  // persistent blocks, 2 CTAs/SM -> all resident
#define PITCH   136                  // bf16 pitch: 17x16B, ldmatrix conflict-free

#define TILE_BYTES (DIM * PITCH * 2)     // 34816
#define FSMEM      (2 * TILE_BYTES)      // 69632  (2 CTAs/SM fits 228KB)
#define KSTEP_B    (16 * PITCH * 2)      // 4352 bytes per k16 step

// ---------------- device globals (no allocs allowed) ----------------------
__device__ float    g_part[3][NSLAB][DIM * DIM]; // partial grams (permuted layout)
__device__ double   g_bsum[64];
__device__ unsigned g_bar[3];                    // [0],[1] barriers, [2] done

__device__ __forceinline__ uint32_t smem_u32(const void* p) {
    uint32_t a;
    asm("{ .reg .u64 t; cvta.to.shared.u64 t, %1; cvt.u32.u64 %0, t; }"
        : "=r"(a) : "l"(p));
    return a;
}

#define LDMX4T(r0, r1, r2, r3, addr) \
    asm volatile("ldmatrix.sync.aligned.m8n8.x4.trans.shared.b16 {%0,%1,%2,%3}, [%4];" \
        : "=r"(r0), "=r"(r1), "=r"(r2), "=r"(r3) : "r"(addr))

#define MMA16816(d, a, b) \
    asm volatile("mma.sync.aligned.m16n8k16.row.col.f32.bf16.bf16.f32 " \
        "{%0,%1,%2,%3}, {%4,%5,%6,%7}, {%8,%9}, {%0,%1,%2,%3};" \
        : "+f"((d)[0]), "+f"((d)[1]), "+f"((d)[2]), "+f"((d)[3]) \
        : "r"((a)[0]), "r"((a)[1]), "r"((a)[2]), "r"((a)[3]), \
          "r"((b)[0]), "r"((b)[1]))

// device-wide barrier (all NB blocks resident by construction)
__device__ __forceinline__ void gbar(int id) {
    __syncthreads();
    if (threadIdx.x == 0) {
        __threadfence();
        atomicAdd(&g_bar[id], 1u);
        while (*(volatile unsigned*)&g_bar[id] < NB) __nanosleep(32);
        __threadfence();
    }
    __syncthreads();
}

// normalize 128x128 f32 slab -> bf16 tile in NATURAL [row][dim] layout.
// Loads are front-batched (MLP=16); norm via full shfl (all lanes get sum).
__device__ __forceinline__ void build_tile(const float* __restrict__ src,
                                           __nv_bfloat16* dst,
                                           int lane, int w)
{
    const float4* s4 = reinterpret_cast<const float4*>(src);
    float4 v[16];
#pragma unroll
    for (int i = 0; i < 16; i++)                 // row = i*8 + w, col = lane*4
        v[i] = s4[(i * 8 + w) * 32 + lane];
#pragma unroll
    for (int i = 0; i < 16; i++) {
        float s = v[i].x * v[i].x + v[i].y * v[i].y
                + v[i].z * v[i].z + v[i].w * v[i].w;
#pragma unroll
        for (int off = 16; off > 0; off >>= 1)
            s += __shfl_xor_sync(0xffffffffu, s, off);
        float inv = 1.0f / fmaxf(sqrtf(s), 1e-8f);
        __nv_bfloat162 h0 = __floats2bfloat162_rn(v[i].x * inv, v[i].y * inv);
        __nv_bfloat162 h1 = __floats2bfloat162_rn(v[i].z * inv, v[i].w * inv);
        uint2 pk = { *reinterpret_cast<uint32_t*>(&h0),
                     *reinterpret_cast<uint32_t*>(&h1) };
        *reinterpret_cast<uint2*>(&dst[(i * 8 + w) * PITCH + lane * 4]) = pk;
    }
}

extern "C" __global__ void __launch_bounds__(256, 2)
fused_kernel(const float* __restrict__ Q, const float* __restrict__ K,
             float* __restrict__ out)
{
    extern __shared__ char smem[];
    __nv_bfloat16* tA = reinterpret_cast<__nv_bfloat16*>(smem);
    __nv_bfloat16* tB = tA + DIM * PITCH;
    const uint32_t sAaddr = smem_u32(tA);
    const uint32_t sBaddr = smem_u32(tB);

    const int t    = threadIdx.x;
    const int lane = t & 31;
    const int w    = t >> 5;
    const int bid  = blockIdx.x;

    // ---- phase 1: one gram task per block ---------------------------------
    {
        const int gram = bid >> 6;           // 0=QQ, 1=KK, 2=QK
        const int slab = bid & 63;
        const float* srcA = ((gram == 1) ? K : Q) + (size_t)slab * KSLAB * DIM;

        build_tile(srcA, tA, lane, w);
        if (gram == 2)
            build_tile(K + (size_t)slab * KSLAB * DIM, tB, lane, w);
        __syncthreads();
        const uint32_t sB_use = (gram == 2) ? sBaddr : sAaddr;

        // warp tile: 32 M-rows x 64 N-cols
        const int m0 = (w & 3) * 32;
        const int n0 = (w >> 2) * 64;

        // trans-ldmatrix lane addressing (source layout [k][dim]):
        // A groups: i = lane>>3: mh=i&1, kh=i>>1 -> r0..r3 = A frag order
        // B groups: kh=i&1, nh=i>>1 -> {r0,r1} n-low frag, {r2,r3} n-high frag
        const int gi = lane >> 3, gj = lane & 7;
        const uint32_t aOff = (uint32_t)((((gi >> 1) * 8 + gj) * PITCH
                                         + (gi & 1) * 8) * 2);
        const uint32_t bOff = (uint32_t)((((gi & 1) * 8 + gj) * PITCH
                                         + (gi >> 1) * 8) * 2);
        const uint32_t aBase = sAaddr + aOff + (uint32_t)(m0 * 2);
        const uint32_t bBase = sB_use + bOff + (uint32_t)(n0 * 2);

        float acc[2][8][4];
#pragma unroll
        for (int mt = 0; mt < 2; mt++)
#pragma unroll
            for (int nt = 0; nt < 8; nt++)
#pragma unroll
                for (int r = 0; r < 4; r++) acc[mt][nt][r] = 0.0f;

#pragma unroll
        for (int ks = 0; ks < 8; ks++) {
            const uint32_t kOff = (uint32_t)ks * KSTEP_B;
            uint32_t a[2][4];
#pragma unroll
            for (int mt = 0; mt < 2; mt++)
                LDMX4T(a[mt][0], a[mt][1], a[mt][2], a[mt][3],
                       aBase + kOff + (uint32_t)(mt * 32));  // +16 dims
            uint32_t b[8][2];
#pragma unroll
            for (int nt4 = 0; nt4 < 4; nt4++) {
                uint32_t r0, r1, r2, r3;
                LDMX4T(r0, r1, r2, r3, bBase + kOff + (uint32_t)(nt4 * 32));
                b[nt4 * 2][0] = r0;     b[nt4 * 2][1] = r1;
                b[nt4 * 2 + 1][0] = r2; b[nt4 * 2 + 1][1] = r3;
            }
#pragma unroll
            for (int mt = 0; mt < 2; mt++)
#pragma unroll
                for (int nt = 0; nt < 8; nt++)
                    MMA16816(acc[mt][nt], a[mt], b[nt]);
        }

        // permuted-coalesced partial store (same permutation for every task)
        float* outp = &g_part[gram][slab][0];
#pragma unroll
        for (int mt = 0; mt < 2; mt++)
#pragma unroll
            for (int nt = 0; nt < 8; nt++)
#pragma unroll
                for (int r = 0; r < 4; r++)
                    outp[w * 2048 + (mt * 8 + nt) * 128 + r * 32 + lane]
                        = acc[mt][nt][r];
    }

    gbar(0);

    // ---- phase 2: reduce over slabs (blocks 0..63) ------------------------
    if (bid < 64) {
        const int idx = bid * 256 + t;                  // [0, 16384)
        const float* p0 = &g_part[0][0][0];
        const float* p1 = &g_part[1][0][0];
        const float* p2 = &g_part[2][0][0];
        double sq = 0.0, sk = 0.0, sx = 0.0;
#pragma unroll 8
        for (int s = 0; s < NSLAB; s++) {
            sq += (double)p0[s * 16384 + idx];
            sk += (double)p1[s * 16384 + idx];
            sx += (double)p2[s * 16384 + idx];
        }
        double c = sq * sq + sk * sk - 2.0 * sx * sx;
#pragma unroll
        for (int off = 16; off > 0; off >>= 1)
            c += __shfl_xor_sync(0xffffffffu, c, off);

        double* wsum = reinterpret_cast<double*>(smem);  // reuse tile smem
        if (lane == 0) wsum[w] = c;
        __syncthreads();
        if (t == 0) {
            double s = 0.0;
#pragma unroll
            for (int ww = 0; ww < 8; ww++) s += wsum[ww];
            g_bsum[bid] = s;
        }
    }

    gbar(1);

    // ---- phase 3: final scalar (block 0) ----------------------------------
    if (bid == 0 && w == 0) {
        double s = g_bsum[lane] + g_bsum[lane + 32];
#pragma unroll
        for (int off = 16; off > 0; off >>= 1)
            s += __shfl_xor_sync(0xffffffffu, s, off);
        if (lane == 0)
            out[0] = (float)(s / (8192.0 * 8191.0));
    }

    // ---- exit protocol: self-resetting barriers across graph replays ------
    __syncthreads();
    if (t == 0) {
        __threadfence();
        atomicAdd(&g_bar[2], 1u);
        if (bid == 0) {
            while (*(volatile unsigned*)&g_bar[2] < NB) __nanosleep(32);
            g_bar[0] = 0u;
            g_bar[1] = 0u;
            __threadfence();
            g_bar[2] = 0u;
        }
    }
}

extern "C" void kernel_launch(void* const* d_in, const int* in_sizes, int n_in,
                              void* d_out, int out_size)
{
    (void)in_sizes; (void)n_in; (void)out_size;
    const float* Q = (const float*)d_in[0];
    const float* K = (const float*)d_in[1];

    cudaFuncSetAttribute(fused_kernel,
                         cudaFuncAttributeMaxDynamicSharedMemorySize, FSMEM);
    fused_kernel<<<NB, 256, FSMEM>>>(Q, K, (float*)d_out);
}